// round 4
// baseline (speedup 1.0000x reference)
#include <cuda_runtime.h>
#include <cstdint>

#define BATCH 16384
#define NEG 5
#define ROWS 7                       // u, v, 5 negs
#define WARPS_PER_BLOCK 8
#define THREADS (WARPS_PER_BLOCK * 32)        // 256
#define NBLOCKS (BATCH / WARPS_PER_BLOCK)     // 2048

__device__ float g_partials[NBLOCKS];
__device__ unsigned int g_count;              // zero-init; last block resets

__device__ __forceinline__ float logsig(float x) {
    // stable log(sigmoid(x)) = min(x,0) - log1p(exp(-|x|))
    return fminf(x, 0.0f) - log1pf(expf(-fabsf(x)));
}

__global__ void __launch_bounds__(THREADS)
sg_fused(const float* __restrict__ emb,
         const int* __restrict__ centers,
         const int* __restrict__ contexts,
         const int* __restrict__ negs,
         float* __restrict__ out) {
    // Staging: [warp][row][lane] float4 -> 8 * 7 * 512B = 28 KB
    __shared__ __align__(16) float4 stage[WARPS_PER_BLOCK][ROWS][32];
    __shared__ float sm[WARPS_PER_BLOCK];
    __shared__ bool is_last;

    const int lane = threadIdx.x & 31;
    const int warp = threadIdx.x >> 5;
    const int b = blockIdx.x * WARPS_PER_BLOCK + warp;

    // One divergent LDG covers all 7 indices for this element (lanes 0..6).
    int idx = 0;
    if (lane == 0)      idx = centers[b];
    else if (lane == 1) idx = contexts[b];
    else if (lane < 7)  idx = negs[b * NEG + (lane - 2)];

    // Issue all 7 row copies async (no dest registers -> true MLP=7/warp,
    // hundreds of rows in flight per SM).
    const float4* e4 = reinterpret_cast<const float4*>(emb);
    #pragma unroll
    for (int r = 0; r < ROWS; r++) {
        int row = __shfl_sync(0xffffffffu, idx, r);
        const float4* src = e4 + (size_t)row * 32 + lane;
        uint32_t dst = (uint32_t)__cvta_generic_to_shared(&stage[warp][r][lane]);
        asm volatile("cp.async.cg.shared.global [%0], [%1], 16;\n"
                     :: "r"(dst), "l"(src));
    }
    asm volatile("cp.async.commit_group;\n");
    asm volatile("cp.async.wait_group 0;\n" ::: "memory");
    __syncwarp();

    // Conflict-free LDS.128 reads (lane i -> bank-consecutive 16B).
    const float4 u  = stage[warp][0][lane];
    const float4 v  = stage[warp][1][lane];
    const float4 w0 = stage[warp][2][lane];
    const float4 w1 = stage[warp][3][lane];
    const float4 w2 = stage[warp][4][lane];
    const float4 w3 = stage[warp][5][lane];
    const float4 w4 = stage[warp][6][lane];

    // sum_k (u . nv_k) == u . (sum_k nv_k)
    float4 ns;
    ns.x = w0.x + w1.x + w2.x + w3.x + w4.x;
    ns.y = w0.y + w1.y + w2.y + w3.y + w4.y;
    ns.z = w0.z + w1.z + w2.z + w3.z + w4.z;
    ns.w = w0.w + w1.w + w2.w + w3.w + w4.w;

    float pos = u.x * v.x  + u.y * v.y  + u.z * v.z  + u.w * v.w;
    float neg = u.x * ns.x + u.y * ns.y + u.z * ns.z + u.w * ns.w;

    #pragma unroll
    for (int o = 16; o > 0; o >>= 1) {
        pos += __shfl_xor_sync(0xffffffffu, pos, o);
        neg += __shfl_xor_sync(0xffffffffu, neg, o);
    }

    if (lane == 0)
        sm[warp] = logsig(pos) + logsig(-neg);
    __syncthreads();

    if (threadIdx.x == 0) {
        float s = 0.0f;
        #pragma unroll
        for (int i = 0; i < WARPS_PER_BLOCK; i++) s += sm[i];
        g_partials[blockIdx.x] = s;
        __threadfence();
        unsigned int t = atomicAdd(&g_count, 1u);
        is_last = (t == NBLOCKS - 1);
    }
    __syncthreads();

    // Last block: deterministic fixed-order final reduction of 2048 partials.
    if (is_last) {
        __shared__ float red[THREADS];
        float s = 0.0f;
        #pragma unroll
        for (int i = 0; i < NBLOCKS / THREADS; i++)   // 8 per thread
            s += g_partials[threadIdx.x + i * THREADS];
        red[threadIdx.x] = s;
        __syncthreads();
        #pragma unroll
        for (int o = THREADS / 2; o > 0; o >>= 1) {
            if (threadIdx.x < o) red[threadIdx.x] += red[threadIdx.x + o];
            __syncthreads();
        }
        if (threadIdx.x == 0) {
            out[0] = -red[0];
            g_count = 0;   // reset for next graph replay (determinism)
        }
    }
}

extern "C" void kernel_launch(void* const* d_in, const int* in_sizes, int n_in,
                              void* d_out, int out_size) {
    const float* emb      = (const float*)d_in[0];
    const int*   centers  = (const int*)  d_in[1];
    const int*   contexts = (const int*)  d_in[2];
    const int*   negs     = (const int*)  d_in[3];
    float*       out      = (float*)d_out;

    sg_fused<<<NBLOCKS, THREADS>>>(emb, centers, contexts, negs, out);
}